// round 7
// baseline (speedup 1.0000x reference)
#include <cuda_runtime.h>

// heightfield: [16,1,512,512] f32 -> same shape.
// out[w] = 1 - clip( max_{r=1..16}( pad(row)[w+r] - r/10 ) - row[w], 0, 1 )
// 8 outputs per thread (two quads), footprint [c0, c0+24) via 6 aligned
// float4 loads. Thread-local bias g[k] = v[k] - 0.1k. Shared 9-wide core max
// g[8..16] + suffix/prefix fixup chains. No smem, no shuffles.

#define IM 512
#define NEG (-1e30f)
#define THREADS 256

__global__ __launch_bounds__(THREADS) void shadow_ov8(const float* __restrict__ in,
                                                      float* __restrict__ out) {
    const int gtid = blockIdx.x * blockDim.x + threadIdx.x;
    const int c0 = gtid << 3;              // element index (row-major), 8 per thread
    const int col = c0 & (IM - 1);         // column within row (0..504, step 8)

    const float* p = in + c0;

    float g[24];
    // quads 0,1 always fully in-row (col+4 <= 508)
    {
        float4 v = *reinterpret_cast<const float4*>(p);
        g[0] = v.x; g[1] = v.y - 0.1f; g[2] = v.z - 0.2f; g[3] = v.w - 0.3f;
        float4 u = *reinterpret_cast<const float4*>(p + 4);
        g[4] = u.x - 0.4f; g[5] = u.y - 0.5f; g[6] = u.z - 0.6f; g[7] = u.w - 0.7f;
    }
    #pragma unroll
    for (int i = 2; i < 6; ++i) {
        if (col + 4 * i <= IM - 4) {       // quad fully inside this row
            float4 v = *reinterpret_cast<const float4*>(p + 4 * i);
            g[4*i+0] = v.x - 0.1f * (4*i+0);
            g[4*i+1] = v.y - 0.1f * (4*i+1);
            g[4*i+2] = v.z - 0.1f * (4*i+2);
            g[4*i+3] = v.w - 0.1f * (4*i+3);
        } else {                           // beyond row end: never wins
            g[4*i+0] = NEG; g[4*i+1] = NEG; g[4*i+2] = NEG; g[4*i+3] = NEG;
        }
    }

    // core: max over g[8..16], shared by all 8 windows [j+1, j+16]
    float core = g[8];
    #pragma unroll
    for (int k = 9; k <= 16; ++k) core = fmaxf(core, g[k]);

    // suffix maxes over g[1..7]: suf[k] = max(g[k..7])
    float suf[8];
    suf[7] = g[7];
    #pragma unroll
    for (int k = 6; k >= 1; --k) suf[k] = fmaxf(g[k], suf[k + 1]);

    // prefix maxes over g[17..23]: pre[k] = max(g[17..k])
    float pre[24];
    pre[17] = g[17];
    #pragma unroll
    for (int k = 18; k <= 23; ++k) pre[k] = fmaxf(pre[k - 1], g[k]);

    float m[8];
    m[0] = fmaxf(core, suf[1]);
    #pragma unroll
    for (int j = 1; j <= 6; ++j) m[j] = fmaxf(fmaxf(core, suf[j + 1]), pre[16 + j]);
    m[7] = fmaxf(core, pre[23]);

    float4 o0, o1;
    o0.x = __saturatef(1.0f + (g[0] - m[0]));
    o0.y = __saturatef(1.0f + (g[1] - m[1]));
    o0.z = __saturatef(1.0f + (g[2] - m[2]));
    o0.w = __saturatef(1.0f + (g[3] - m[3]));
    o1.x = __saturatef(1.0f + (g[4] - m[4]));
    o1.y = __saturatef(1.0f + (g[5] - m[5]));
    o1.z = __saturatef(1.0f + (g[6] - m[6]));
    o1.w = __saturatef(1.0f + (g[7] - m[7]));

    *reinterpret_cast<float4*>(out + c0) = o0;
    *reinterpret_cast<float4*>(out + c0 + 4) = o1;
}

extern "C" void kernel_launch(void* const* d_in, const int* in_sizes, int n_in,
                              void* d_out, int out_size) {
    const float* in = (const float*)d_in[0];
    float* out = (float*)d_out;
    const int n = in_sizes[0];                 // 4,194,304
    const int threads_total = n / 8;           // 524,288
    shadow_ov8<<<threads_total / THREADS, THREADS>>>(in, out);
}